// round 10
// baseline (speedup 1.0000x reference)
#include <cuda_runtime.h>
#include <cuda_fp16.h>

// ============================================================================
// AttentionGate3D — round 10: occupancy attack. CTA tile 128M x 64N,
// warp tile 32x32, __launch_bounds__(256,3) => 24 warps/SM (was 16).
// Same streamed cp.async pipeline as round 9 (B fp32 3-stage thread-private,
// A fp16 4-stage, swizzled fp16 sBh double buffer, 1 barrier/32-chunk).
// ============================================================================

#define EPS 1e-5f

constexpr int NB = 2;
constexpr int G  = 256;
constexpr int XC = 128;
constexpr int I  = 128;
constexpr int S  = 32 * 64 * 64;   // 131072

// ---- scratch ----
__device__ __half d_yg[NB * I * S];
__device__ __half d_yx[NB * I * S];
__device__ __align__(16) __half d_whg[I * G];
__device__ __align__(16) __half d_whx[I * XC];
__device__ float  d_z[NB * S];
__device__ float  d_sum_g[NB * I];
__device__ float  d_sq_g [NB * I];
__device__ float  d_sum_x[NB * I];
__device__ float  d_sq_x [NB * I];
__device__ float  d_zstat[2 * NB];
__device__ float  d_cAg[NB * I], d_cBg[NB * I];
__device__ float  d_cAx[NB * I], d_cBx[NB * I];

// ---- W fp32->fp16 pre-convert + stat zeroing ----
__global__ void k_wconv(const float* __restrict__ Wg, const float* __restrict__ Wx) {
    int t = blockIdx.x * 256 + threadIdx.x;
    if (t < I * G)  d_whg[t] = __float2half_rn(Wg[t]);
    if (t < I * XC) d_whx[t] = __float2half_rn(Wx[t]);
    if (t < NB * I) {
        d_sum_g[t] = 0.f; d_sq_g[t] = 0.f;
        d_sum_x[t] = 0.f; d_sq_x[t] = 0.f;
    }
}
__global__ void k_zero2() {
    int t = threadIdx.x;
    if (t < 2 * NB) d_zstat[t] = 0.f;
}

// ---- MMA helpers ----
__device__ __forceinline__ void ldsm_x4(unsigned (&r)[4], unsigned addr) {
    asm volatile("ldmatrix.sync.aligned.m8n8.x4.shared.b16 {%0,%1,%2,%3}, [%4];"
        : "=r"(r[0]), "=r"(r[1]), "=r"(r[2]), "=r"(r[3]) : "r"(addr));
}
__device__ __forceinline__ void ldsm_x4_t(unsigned (&r)[4], unsigned addr) {
    asm volatile("ldmatrix.sync.aligned.m8n8.x4.trans.shared.b16 {%0,%1,%2,%3}, [%4];"
        : "=r"(r[0]), "=r"(r[1]), "=r"(r[2]), "=r"(r[3]) : "r"(addr));
}
__device__ __forceinline__ void mma16816(float (&d)[4], const unsigned (&a)[4],
                                         const unsigned (&b)[2]) {
    asm volatile("mma.sync.aligned.m16n8k16.row.col.f32.f16.f16.f32 "
        "{%0,%1,%2,%3}, {%4,%5,%6,%7}, {%8,%9}, {%0,%1,%2,%3};"
        : "+f"(d[0]), "+f"(d[1]), "+f"(d[2]), "+f"(d[3])
        : "r"(a[0]), "r"(a[1]), "r"(a[2]), "r"(a[3]), "r"(b[0]), "r"(b[1]));
}
union H2U { __half2 h; unsigned u; };
__device__ __forceinline__ unsigned pack2h(float a, float b) {
    H2U v; v.h = __floats2half2_rn(a, b); return v.u;
}
__device__ __forceinline__ void cp16(unsigned dst, const void* src) {
    asm volatile("cp.async.cg.shared.global [%0], [%1], 16;" :: "r"(dst), "l"(src));
}
__device__ __forceinline__ void cp_commit() {
    asm volatile("cp.async.commit_group;" ::: "memory");
}
template<int N>
__device__ __forceinline__ void cp_wait() {
    asm volatile("cp.async.wait_group %0;" :: "n"(N) : "memory");
}

// ---- GEMM: y[n,i,p] = sum_c W[i,c]*src[n,c,p] ------------------------------
// CTA tile M=128(i) x N=64(p); 8 warps = 4(M) x 2(N), warp 32M x 32N.
// K in 32-chunks. smem: sS (B fp32, thread-private) 3 x 8KB |
// sAh (W fp16) 4 x 8KB | sBh (fp16 swizzled) 2 x 4KB  = 64KB.
template<int K, bool ISG>
__global__ void __launch_bounds__(256, 3) k_gemm(const float* __restrict__ src) {
    constexpr int NIT2 = K / 32;
    extern __shared__ __align__(16) char smem[];
    const unsigned sS32  = (unsigned)__cvta_generic_to_shared(smem);
    const unsigned sAh32 = (unsigned)__cvta_generic_to_shared(smem + 24576);
    const unsigned sBh32 = (unsigned)__cvta_generic_to_shared(smem + 57344);
    float* sS  = reinterpret_cast<float*>(smem);
    char*  sBh = smem + 57344;

    const __half* wh  = ISG ? d_whg   : d_whx;
    __half* yout = ISG ? d_yg    : d_yx;
    float*  ssum = ISG ? d_sum_g : d_sum_x;
    float*  ssq  = ISG ? d_sq_g  : d_sq_x;

    const int tid  = threadIdx.x;
    const int warp = tid >> 5, lane = tid & 31;
    const int wm = warp >> 1, wn = warp & 1;      // 4(M) x 2(N)
    const int n  = blockIdx.y;
    const int p0 = blockIdx.x * 64;
    const float* srcn = src + (size_t)n * K * S + p0;

    // B staging: channel cst (0..31), point-octet pb (0..7)
    const int cst = tid >> 3;
    const int pb  = tid & 7;
    const float* gp = srcn + (size_t)cst * S + pb * 8;
    // A staging: row arow (0..127), unit parity ah (0/1)
    const int arow = tid >> 1, ah = tid & 1;
    const __half* wsrc = wh + (size_t)arow * K + ah * 8;

    auto issue = [&](int it) {
        // B chunk: stage layout [2 pieces][256 threads][16B] (thread-private)
        unsigned dstB = sS32 + (unsigned)((it % 3) * 8192 + tid * 16);
        const float* s0 = gp + (size_t)it * 32 * S;
        cp16(dstB, s0);
        cp16(dstB + 4096, s0 + 4);
        // A chunk: stage layout [4 units][128 rows][16B]
        unsigned dstA = sAh32 + (unsigned)((it & 3) * 8192 + arow * 16);
        const __half* w0 = wsrc + it * 32;
        cp16(dstA + ah * 2048, w0);
        cp16(dstA + (2 + ah) * 2048, w0 + 16);
    };

    issue(0); cp_commit();
    issue(1); cp_commit();
    issue(2); cp_commit();

    float acc[2][4][4] = {};

    // swizzled STS offset in sBh (row cst = 64 halves = 128B, 8 units)
    const unsigned stso = (unsigned)(cst * 128 + (pb ^ (cst & 7)) * 16);

    for (int it = 0; it < NIT2; it++) {
        cp_wait<2>();                    // group `it` landed (thread-private)
        const float4* rp = reinterpret_cast<const float4*>(
            reinterpret_cast<char*>(sS) + (it % 3) * 8192 + tid * 16);
        float4 w0 = rp[0];
        float4 w1 = rp[256];             // +4096 bytes
        {
            uint4 u;
            u.x = pack2h(w0.x, w0.y); u.y = pack2h(w0.z, w0.w);
            u.z = pack2h(w1.x, w1.y); u.w = pack2h(w1.z, w1.w);
            *reinterpret_cast<uint4*>(sBh + (it & 1) * 4096 + stso) = u;
        }
        __syncthreads();                 // publishes STS(it) + A stage it;
                                         // seals ldsm(it-1) -> safe reuse
        if (it + 3 < NIT2) issue(it + 3);
        cp_commit();

        const unsigned sbb = sBh32 + (unsigned)((it & 1) * 4096);
        const unsigned saa = sAh32 + (unsigned)((it & 3) * 8192);
#pragma unroll
        for (int kh2 = 0; kh2 < 2; kh2++) {
            unsigned afr[2][4];
#pragma unroll
            for (int tm = 0; tm < 2; tm++) {
                int row = wm * 32 + tm * 16 + (lane & 15);
                int u   = 2 * kh2 + (lane >> 4);
                ldsm_x4(afr[tm], saa + (unsigned)(u * 2048 + row * 16));
            }
            unsigned bfr[4][2];
#pragma unroll
            for (int h = 0; h < 2; h++) {
                int nb = wn * 4 + 2 * h + ((lane >> 4) & 1);
                int cg = kh2 * 16 + ((lane >> 3) & 1) * 8 + (lane & 7);
                unsigned r4[4];
                ldsm_x4_t(r4, sbb + (unsigned)(cg * 128 +
                          ((nb ^ (lane & 7)) * 16)));
                bfr[2 * h][0]     = r4[0]; bfr[2 * h][1]     = r4[1];
                bfr[2 * h + 1][0] = r4[2]; bfr[2 * h + 1][1] = r4[3];
            }
#pragma unroll
            for (int tm = 0; tm < 2; tm++)
#pragma unroll
                for (int tn = 0; tn < 4; tn++)
                    mma16816(acc[tm][tn], afr[tm], bfr[tn]);
        }
    }

    // epilogue: fp16 store + per-i stats from fp32 accumulators
    __half* yn = yout + (size_t)n * I * S + p0;
#pragma unroll
    for (int tm = 0; tm < 2; tm++) {
        int r1 = wm * 32 + tm * 16 + (lane >> 2);
        float s1 = 0.f, q1 = 0.f, s2 = 0.f, q2 = 0.f;
#pragma unroll
        for (int tn = 0; tn < 4; tn++) {
            float* c = acc[tm][tn];
            int col = wn * 32 + tn * 8 + (lane & 3) * 2;
            *reinterpret_cast<__half2*>(yn + (size_t)r1 * S + col) =
                __floats2half2_rn(c[0], c[1]);
            *reinterpret_cast<__half2*>(yn + (size_t)(r1 + 8) * S + col) =
                __floats2half2_rn(c[2], c[3]);
            s1 += c[0] + c[1]; q1 += c[0] * c[0] + c[1] * c[1];
            s2 += c[2] + c[3]; q2 += c[2] * c[2] + c[3] * c[3];
        }
#pragma unroll
        for (int off = 2; off > 0; off >>= 1) {
            s1 += __shfl_down_sync(0xFFFFFFFFu, s1, off, 4);
            q1 += __shfl_down_sync(0xFFFFFFFFu, q1, off, 4);
            s2 += __shfl_down_sync(0xFFFFFFFFu, s2, off, 4);
            q2 += __shfl_down_sync(0xFFFFFFFFu, q2, off, 4);
        }
        if ((lane & 3) == 0) {
            atomicAdd(&ssum[n * I + r1], s1);
            atomicAdd(&ssq [n * I + r1], q1);
            atomicAdd(&ssum[n * I + r1 + 8], s2);
            atomicAdd(&ssq [n * I + r1 + 8], q2);
        }
    }
}

// ---- coefs ------------------------------------------------------------------
__global__ void k_coefs(const float* __restrict__ gam_g, const float* __restrict__ bet_g,
                        const float* __restrict__ gam_x, const float* __restrict__ bet_x) {
    int t = threadIdx.x;
    if (t < NB * I) {
        int i = t & (I - 1);
        const float inv = 1.f / (float)S;
        float m   = d_sum_g[t] * inv;
        float var = fmaxf(d_sq_g[t] * inv - m * m, 0.f);
        float A   = gam_g[i] * rsqrtf(var + EPS);
        d_cAg[t] = A; d_cBg[t] = bet_g[i] - m * A;
        m   = d_sum_x[t] * inv;
        var = fmaxf(d_sq_x[t] * inv - m * m, 0.f);
        A   = gam_x[i] * rsqrtf(var + EPS);
        d_cAx[t] = A; d_cBx[t] = bet_x[i] - m * A;
    }
}

// ---- combine: z = Wpsi . relu(Ag*yg+Bg + Ax*yx+Bx), + z stats ---------------
__global__ void __launch_bounds__(256) k_combine(const float* __restrict__ Wpsi) {
    __shared__ float sc[5 * I];
    const int tid = threadIdx.x;
    const int n   = blockIdx.y;
    const int p0  = blockIdx.x * 1024;
    if (tid < I) {
        sc[tid]         = d_cAg[n * I + tid];
        sc[I + tid]     = d_cBg[n * I + tid];
        sc[2 * I + tid] = d_cAx[n * I + tid];
        sc[3 * I + tid] = d_cBx[n * I + tid];
        sc[4 * I + tid] = Wpsi[tid];
    }
    __syncthreads();
    const __half* ygb = d_yg + (size_t)n * I * S + p0 + tid * 4;
    const __half* yxb = d_yx + (size_t)n * I * S + p0 + tid * 4;
    float za[4] = {0.f, 0.f, 0.f, 0.f};

#pragma unroll 4
    for (int i = 0; i < I; i++) {
        uint2 ua = *reinterpret_cast<const uint2*>(ygb + (size_t)i * S);
        uint2 ub = *reinterpret_cast<const uint2*>(yxb + (size_t)i * S);
        float Ag = sc[i], Ax = sc[2 * I + i];
        float C  = sc[I + i] + sc[3 * I + i];
        float w  = sc[4 * I + i];
        H2U a0, a1, b0, b1;
        a0.u = ua.x; a1.u = ua.y; b0.u = ub.x; b1.u = ub.y;
        float2 fa0 = __half22float2(a0.h), fa1 = __half22float2(a1.h);
        float2 fb0 = __half22float2(b0.h), fb1 = __half22float2(b1.h);
        za[0] += w * fmaxf(fmaf(Ag, fa0.x, fmaf(Ax, fb0.x, C)), 0.f);
        za[1] += w * fmaxf(fmaf(Ag, fa0.y, fmaf(Ax, fb0.y, C)), 0.f);
        za[2] += w * fmaxf(fmaf(Ag, fa1.x, fmaf(Ax, fb1.x, C)), 0.f);
        za[3] += w * fmaxf(fmaf(Ag, fa1.y, fmaf(Ax, fb1.y, C)), 0.f);
    }
    *reinterpret_cast<float4*>(&d_z[n * S + p0 + tid * 4]) =
        make_float4(za[0], za[1], za[2], za[3]);

    float s = za[0] + za[1] + za[2] + za[3];
    float q = za[0]*za[0] + za[1]*za[1] + za[2]*za[2] + za[3]*za[3];
#pragma unroll
    for (int off = 16; off > 0; off >>= 1) {
        s += __shfl_down_sync(0xFFFFFFFFu, s, off);
        q += __shfl_down_sync(0xFFFFFFFFu, q, off);
    }
    __shared__ float rs[8], rq[8];
    int wid = tid >> 5, ln = tid & 31;
    if (ln == 0) { rs[wid] = s; rq[wid] = q; }
    __syncthreads();
    if (tid == 0) {
        float st = 0.f, qt = 0.f;
#pragma unroll
        for (int w2 = 0; w2 < 8; w2++) { st += rs[w2]; qt += rq[w2]; }
        atomicAdd(&d_zstat[n], st);
        atomicAdd(&d_zstat[NB + n], qt);
    }
}

// ---- fused alpha+mul: out = x * sigmoid(A*z+B) ------------------------------
__global__ void k_mul(const float* __restrict__ x, float* __restrict__ out,
                      const float* __restrict__ gam_p, const float* __restrict__ bet_p) {
    const int idx = blockIdx.x * blockDim.x + threadIdx.x;   // float4 index
    const int n   = idx >> 22;
    const int p4  = idx & (S / 4 - 1);
    const float inv = 1.f / (float)S;
    float m   = d_zstat[n] * inv;
    float var = fmaxf(d_zstat[NB + n] * inv - m * m, 0.f);
    float A   = gam_p[0] * rsqrtf(var + EPS);
    float B   = bet_p[0] - m * A;
    float4 z  = *reinterpret_cast<const float4*>(&d_z[n * S + p4 * 4]);
    float4 xv = reinterpret_cast<const float4*>(x)[idx];
    float4 o;
    o.x = xv.x / (1.f + __expf(-fmaf(A, z.x, B)));
    o.y = xv.y / (1.f + __expf(-fmaf(A, z.y, B)));
    o.z = xv.z / (1.f + __expf(-fmaf(A, z.z, B)));
    o.w = xv.w / (1.f + __expf(-fmaf(A, z.w, B)));
    reinterpret_cast<float4*>(out)[idx] = o;
}

// ============================================================================
extern "C" void kernel_launch(void* const* d_in, const int* in_sizes, int n_in,
                              void* d_out, int out_size) {
    const float* g     = (const float*)d_in[0];
    const float* x     = (const float*)d_in[1];
    const float* Wg    = (const float*)d_in[2];
    const float* Wx    = (const float*)d_in[3];
    const float* Wpsi  = (const float*)d_in[4];
    const float* gam_g = (const float*)d_in[5];
    const float* bet_g = (const float*)d_in[6];
    const float* gam_x = (const float*)d_in[7];
    const float* bet_x = (const float*)d_in[8];
    const float* gam_p = (const float*)d_in[9];
    const float* bet_p = (const float*)d_in[10];
    float* out = (float*)d_out;

    const int SMEM = 24576 + 32768 + 8192;         // 65536 per CTA
    cudaFuncSetAttribute(k_gemm<G,  true >,
                         cudaFuncAttributeMaxDynamicSharedMemorySize, SMEM);
    cudaFuncSetAttribute(k_gemm<XC, false>,
                         cudaFuncAttributeMaxDynamicSharedMemorySize, SMEM);

    dim3 ggrid(S / 64, NB);                        // 2048 x 2

    // order keeps k_gemm<G> at launch slot 4 (ncu capture)
    k_wconv<<<128, 256>>>(Wg, Wx);
    k_gemm<XC, false><<<ggrid, 256, SMEM>>>(x);
    k_zero2<<<1, 32>>>();
    k_gemm<G,  true ><<<ggrid, 256, SMEM>>>(g);

    k_coefs<<<1, 256>>>(gam_g, bet_g, gam_x, bet_x);

    dim3 cgrid(S / 1024, NB);                      // 128 x 2
    k_combine<<<cgrid, 256>>>(Wpsi);

    int total4 = NB * XC * S / 4;                  // 8,388,608 float4
    k_mul<<<total4 / 256, 256>>>(x, out, gam_p, bet_p);
}

// round 11
// speedup vs baseline: 1.3588x; 1.3588x over previous
#include <cuda_runtime.h>
#include <cuda_fp16.h>
#include <cstdint>

// ============================================================================
// AttentionGate3D — round 11: round-9 GEMM (best: 100.7us) with the B fp32
// tile copied by cp.async.bulk (UBLKCP, 1 insn per 512B row, mbarrier ring)
// instead of 1024 LDGSTS per chunk — attacks the measured MIO-issue bound.
// A path / conversion / MMA / epilogue identical to round 9.
// ============================================================================

#define EPS 1e-5f

constexpr int NB = 2;
constexpr int G  = 256;
constexpr int XC = 128;
constexpr int I  = 128;
constexpr int S  = 32 * 64 * 64;   // 131072

// ---- scratch ----
__device__ __half d_yg[NB * I * S];
__device__ __half d_yx[NB * I * S];
__device__ __align__(16) __half d_whg[I * G];
__device__ __align__(16) __half d_whx[I * XC];
__device__ float  d_z[NB * S];
__device__ float  d_sum_g[NB * I];
__device__ float  d_sq_g [NB * I];
__device__ float  d_sum_x[NB * I];
__device__ float  d_sq_x [NB * I];
__device__ float  d_zstat[2 * NB];
__device__ float  d_cAg[NB * I], d_cBg[NB * I];
__device__ float  d_cAx[NB * I], d_cBx[NB * I];

// ---- smem map (bytes): mbars | B fp32 3x16KB | A fp16 4x8KB | sBh 2x8KB ----
constexpr int SM_MB  = 0;        // 3 x 8B mbarriers
constexpr int SM_B   = 128;
constexpr int SM_A   = SM_B + 3 * 16384;    // 49280
constexpr int SM_BH  = SM_A + 4 * 8192;     // 82048 (128B aligned)
constexpr int SM_TOT = SM_BH + 2 * 8192;    // 98432

// ---- W fp32->fp16 pre-convert + stat zeroing ----
__global__ void k_wconv(const float* __restrict__ Wg, const float* __restrict__ Wx) {
    int t = blockIdx.x * 256 + threadIdx.x;
    if (t < I * G)  d_whg[t] = __float2half_rn(Wg[t]);
    if (t < I * XC) d_whx[t] = __float2half_rn(Wx[t]);
    if (t < NB * I) {
        d_sum_g[t] = 0.f; d_sq_g[t] = 0.f;
        d_sum_x[t] = 0.f; d_sq_x[t] = 0.f;
    }
}
__global__ void k_zero2() {
    int t = threadIdx.x;
    if (t < 2 * NB) d_zstat[t] = 0.f;
}

// ---- PTX helpers ----
__device__ __forceinline__ void ldsm_x4(unsigned (&r)[4], unsigned addr) {
    asm volatile("ldmatrix.sync.aligned.m8n8.x4.shared.b16 {%0,%1,%2,%3}, [%4];"
        : "=r"(r[0]), "=r"(r[1]), "=r"(r[2]), "=r"(r[3]) : "r"(addr));
}
__device__ __forceinline__ void ldsm_x4_t(unsigned (&r)[4], unsigned addr) {
    asm volatile("ldmatrix.sync.aligned.m8n8.x4.trans.shared.b16 {%0,%1,%2,%3}, [%4];"
        : "=r"(r[0]), "=r"(r[1]), "=r"(r[2]), "=r"(r[3]) : "r"(addr));
}
__device__ __forceinline__ void mma16816(float (&d)[4], const unsigned (&a)[4],
                                         const unsigned (&b)[2]) {
    asm volatile("mma.sync.aligned.m16n8k16.row.col.f32.f16.f16.f32 "
        "{%0,%1,%2,%3}, {%4,%5,%6,%7}, {%8,%9}, {%0,%1,%2,%3};"
        : "+f"(d[0]), "+f"(d[1]), "+f"(d[2]), "+f"(d[3])
        : "r"(a[0]), "r"(a[1]), "r"(a[2]), "r"(a[3]), "r"(b[0]), "r"(b[1]));
}
union H2U { __half2 h; unsigned u; };
__device__ __forceinline__ unsigned pack2h(float a, float b) {
    H2U v; v.h = __floats2half2_rn(a, b); return v.u;
}
__device__ __forceinline__ void cp16(unsigned dst, const void* src) {
    asm volatile("cp.async.cg.shared.global [%0], [%1], 16;" :: "r"(dst), "l"(src));
}
__device__ __forceinline__ void cp_commit() {
    asm volatile("cp.async.commit_group;" ::: "memory");
}
template<int N>
__device__ __forceinline__ void cp_wait() {
    asm volatile("cp.async.wait_group %0;" :: "n"(N) : "memory");
}
__device__ __forceinline__ void bulk_cp(unsigned dst, const void* src,
                                        unsigned bytes, unsigned mbar) {
    asm volatile("cp.async.bulk.shared::cta.global.mbarrier::complete_tx::bytes "
                 "[%0], [%1], %2, [%3];"
                 :: "r"(dst), "l"(src), "r"(bytes), "r"(mbar) : "memory");
}
#define MBAR_INIT(mb, c) asm volatile("mbarrier.init.shared.b64 [%0], %1;" :: "r"(mb), "r"(c) : "memory")
#define MBAR_EXPECT_TX(mb, b) asm volatile("mbarrier.arrive.expect_tx.shared.b64 _, [%0], %1;" :: "r"(mb), "r"(b) : "memory")
__device__ __forceinline__ void mbar_wait(uint32_t mb, uint32_t parity) {
    asm volatile(
        "{\n\t.reg .pred P;\n\t"
        "LW_%=:\n\t"
        "mbarrier.try_wait.parity.acquire.cta.shared::cta.b64 P, [%0], %1, 0x989680;\n\t"
        "@!P bra LW_%=;\n\t}"
        :: "r"(mb), "r"(parity) : "memory");
}

// ---- GEMM: y[n,i,p] = sum_c W[i,c]*src[n,c,p] ------------------------------
// CTA tile M=128(i) x N=128(p); 8 warps = 2(M) x 4(N), warp 64M x 32N.
// K in 32-chunks. B fp32 chunk (32 rows x 512B) arrives via 32 cp.async.bulk
// into a 3-stage mbarrier ring; A fp16 via 4-stage cp.async.cg FIFO;
// cvt -> swizzled fp16 sBh double buffer; 1 barrier per chunk.
template<int K, bool ISG>
__global__ void __launch_bounds__(256, 2) k_gemm(const float* __restrict__ src) {
    constexpr int NIT2 = K / 32;
    extern __shared__ __align__(128) char smem[];
    const unsigned smb   = (unsigned)__cvta_generic_to_shared(smem);
    const unsigned sB32  = smb + SM_B;
    const unsigned sAh32 = smb + SM_A;
    const unsigned sBh32 = smb + SM_BH;
    float* sS  = reinterpret_cast<float*>(smem + SM_B);
    char*  sBh = smem + SM_BH;

    const __half* wh  = ISG ? d_whg   : d_whx;
    __half* yout = ISG ? d_yg    : d_yx;
    float*  ssum = ISG ? d_sum_g : d_sum_x;
    float*  ssq  = ISG ? d_sq_g  : d_sq_x;

    const int tid  = threadIdx.x;
    const int warp = tid >> 5, lane = tid & 31;
    const int wm = warp >> 2, wn = warp & 3;
    const int n  = blockIdx.y;
    const int p0 = blockIdx.x * 128;
    const float* srcn = src + (size_t)n * K * S + p0;

    // readback role: channel cst (0..15 -> rows cst, cst+16), pts pb (0..15)
    const int cst = tid >> 4;
    const int pb  = tid & 15;
    // A staging role: row arow (0..127), quarter-pair ah (0/1)
    const int arow = tid >> 1, ah = tid & 1;
    const __half* wsrc = wh + (size_t)arow * K + ah * 8;

    // B: one bulk copy per 512B channel row, issued by tid 0
    auto issueB = [&](int it) {
        if (tid == 0) {
            unsigned mb = smb + SM_MB + (it % 3) * 8;
            MBAR_EXPECT_TX(mb, 16384u);
            unsigned dst = sB32 + (unsigned)((it % 3) * 16384);
            const float* s0 = srcn + (size_t)it * 32 * S;
#pragma unroll
            for (int r = 0; r < 32; r++)
                bulk_cp(dst + r * 512, s0 + (size_t)r * S, 512u, mb);
        }
    };
    auto issueA = [&](int it) {
        unsigned dstA = sAh32 + (unsigned)((it & 3) * 8192 + arow * 16);
        const __half* w0 = wsrc + it * 32;
        cp16(dstA + ah * 2048, w0);
        cp16(dstA + (2 + ah) * 2048, w0 + 16);
    };

    if (tid == 0) {
        MBAR_INIT(smb + SM_MB,      1);
        MBAR_INIT(smb + SM_MB + 8,  1);
        MBAR_INIT(smb + SM_MB + 16, 1);
    }
    __syncthreads();

    issueB(0); issueB(1); issueB(2);
    issueA(0); cp_commit();
    issueA(1); cp_commit();
    issueA(2); cp_commit();

    float acc[4][4][4] = {};

    // fp16 STS byte offsets within a 16-row half of sBh (swizzled)
    const int swz  = ((pb >> 1) ^ (cst & 7));
    const int sts0 = (cst * 128 + (swz << 3)       + ((pb & 1) << 2)) * 2;
    const int sts1 = (cst * 128 + ((8 + swz) << 3) + ((pb & 1) << 2)) * 2;

    for (int it = 0; it < NIT2; it++) {
        mbar_wait(smb + SM_MB + (it % 3) * 8, (unsigned)((it / 3) & 1));
        cp_wait<2>();                    // A group `it` landed
        const float4* rp = reinterpret_cast<const float4*>(
            sS + (it % 3) * 4096 + cst * 128 + pb * 4);
        float4 w0 = rp[0];
        float4 w1 = rp[16];              // +64 floats (same row)
        float4 w2 = rp[512];             // row cst+16
        float4 w3 = rp[528];
        {
            char* sb = sBh + (it & 1) * 8192;
            uint2 u;
            u.x = pack2h(w0.x, w0.y); u.y = pack2h(w0.z, w0.w);
            *reinterpret_cast<uint2*>(sb + sts0) = u;
            u.x = pack2h(w1.x, w1.y); u.y = pack2h(w1.z, w1.w);
            *reinterpret_cast<uint2*>(sb + sts1) = u;
            u.x = pack2h(w2.x, w2.y); u.y = pack2h(w2.z, w2.w);
            *reinterpret_cast<uint2*>(sb + 4096 + sts0) = u;
            u.x = pack2h(w3.x, w3.y); u.y = pack2h(w3.z, w3.w);
            *reinterpret_cast<uint2*>(sb + 4096 + sts1) = u;
        }
        __syncthreads();                 // publishes STS(it)+A stage; seals all
                                         // readers of B stage it%3 & sBh/ldsm
        if (it + 3 < NIT2) { issueB(it + 3); issueA(it + 3); }
        cp_commit();

        const unsigned sbb = sBh32 + (unsigned)((it & 1) * 8192);
        const unsigned saa = sAh32 + (unsigned)((it & 3) * 8192);
#pragma unroll
        for (int kh2 = 0; kh2 < 2; kh2++) {
            unsigned afr[4][4];
#pragma unroll
            for (int tm = 0; tm < 4; tm++) {
                int row = wm * 64 + tm * 16 + (lane & 15);
                ldsm_x4(afr[tm], saa + (unsigned)(kh2 * 4096 +
                         (lane >> 4) * 2048 + row * 16));
            }
            unsigned bfr[4][2];
#pragma unroll
            for (int h = 0; h < 2; h++) {
                int nbX  = 2 * h + ((lane >> 4) & 1);
                int c    = ((lane >> 3) & 1) * 8 + (lane & 7);
                int phys = (wn * 4 + nbX) ^ (lane & 7);
                unsigned r4[4];
                ldsm_x4_t(r4, sbb + (unsigned)(kh2 * 4096 +
                          (c * 128 + phys * 8) * 2));
                bfr[2 * h][0]     = r4[0]; bfr[2 * h][1]     = r4[1];
                bfr[2 * h + 1][0] = r4[2]; bfr[2 * h + 1][1] = r4[3];
            }
#pragma unroll
            for (int tm = 0; tm < 4; tm++)
#pragma unroll
                for (int tn = 0; tn < 4; tn++)
                    mma16816(acc[tm][tn], afr[tm], bfr[tn]);
        }
    }

    // epilogue: fp16 store + per-i stats from fp32 accumulators
    __half* yn = yout + (size_t)n * I * S + p0;
#pragma unroll
    for (int tm = 0; tm < 4; tm++) {
        int r1 = wm * 64 + tm * 16 + (lane >> 2);
        float s1 = 0.f, q1 = 0.f, s2 = 0.f, q2 = 0.f;
#pragma unroll
        for (int tn = 0; tn < 4; tn++) {
            float* c = acc[tm][tn];
            int col = wn * 32 + tn * 8 + (lane & 3) * 2;
            *reinterpret_cast<__half2*>(yn + (size_t)r1 * S + col) =
                __floats2half2_rn(c[0], c[1]);
            *reinterpret_cast<__half2*>(yn + (size_t)(r1 + 8) * S + col) =
                __floats2half2_rn(c[2], c[3]);
            s1 += c[0] + c[1]; q1 += c[0] * c[0] + c[1] * c[1];
            s2 += c[2] + c[3]; q2 += c[2] * c[2] + c[3] * c[3];
        }
#pragma unroll
        for (int off = 2; off > 0; off >>= 1) {
            s1 += __shfl_down_sync(0xFFFFFFFFu, s1, off, 4);
            q1 += __shfl_down_sync(0xFFFFFFFFu, q1, off, 4);
            s2 += __shfl_down_sync(0xFFFFFFFFu, s2, off, 4);
            q2 += __shfl_down_sync(0xFFFFFFFFu, q2, off, 4);
        }
        if ((lane & 3) == 0) {
            atomicAdd(&ssum[n * I + r1], s1);
            atomicAdd(&ssq [n * I + r1], q1);
            atomicAdd(&ssum[n * I + r1 + 8], s2);
            atomicAdd(&ssq [n * I + r1 + 8], q2);
        }
    }
}

// ---- coefs ------------------------------------------------------------------
__global__ void k_coefs(const float* __restrict__ gam_g, const float* __restrict__ bet_g,
                        const float* __restrict__ gam_x, const float* __restrict__ bet_x) {
    int t = threadIdx.x;
    if (t < NB * I) {
        int i = t & (I - 1);
        const float inv = 1.f / (float)S;
        float m   = d_sum_g[t] * inv;
        float var = fmaxf(d_sq_g[t] * inv - m * m, 0.f);
        float A   = gam_g[i] * rsqrtf(var + EPS);
        d_cAg[t] = A; d_cBg[t] = bet_g[i] - m * A;
        m   = d_sum_x[t] * inv;
        var = fmaxf(d_sq_x[t] * inv - m * m, 0.f);
        A   = gam_x[i] * rsqrtf(var + EPS);
        d_cAx[t] = A; d_cBx[t] = bet_x[i] - m * A;
    }
}

// ---- combine: z = Wpsi . relu(Ag*yg+Bg + Ax*yx+Bx), + z stats ---------------
__global__ void __launch_bounds__(256) k_combine(const float* __restrict__ Wpsi) {
    __shared__ float sc[5 * I];
    const int tid = threadIdx.x;
    const int n   = blockIdx.y;
    const int p0  = blockIdx.x * 1024;
    if (tid < I) {
        sc[tid]         = d_cAg[n * I + tid];
        sc[I + tid]     = d_cBg[n * I + tid];
        sc[2 * I + tid] = d_cAx[n * I + tid];
        sc[3 * I + tid] = d_cBx[n * I + tid];
        sc[4 * I + tid] = Wpsi[tid];
    }
    __syncthreads();
    const __half* ygb = d_yg + (size_t)n * I * S + p0 + tid * 4;
    const __half* yxb = d_yx + (size_t)n * I * S + p0 + tid * 4;
    float za[4] = {0.f, 0.f, 0.f, 0.f};

#pragma unroll 4
    for (int i = 0; i < I; i++) {
        uint2 ua = *reinterpret_cast<const uint2*>(ygb + (size_t)i * S);
        uint2 ub = *reinterpret_cast<const uint2*>(yxb + (size_t)i * S);
        float Ag = sc[i], Ax = sc[2 * I + i];
        float C  = sc[I + i] + sc[3 * I + i];
        float w  = sc[4 * I + i];
        H2U a0, a1, b0, b1;
        a0.u = ua.x; a1.u = ua.y; b0.u = ub.x; b1.u = ub.y;
        float2 fa0 = __half22float2(a0.h), fa1 = __half22float2(a1.h);
        float2 fb0 = __half22float2(b0.h), fb1 = __half22float2(b1.h);
        za[0] += w * fmaxf(fmaf(Ag, fa0.x, fmaf(Ax, fb0.x, C)), 0.f);
        za[1] += w * fmaxf(fmaf(Ag, fa0.y, fmaf(Ax, fb0.y, C)), 0.f);
        za[2] += w * fmaxf(fmaf(Ag, fa1.x, fmaf(Ax, fb1.x, C)), 0.f);
        za[3] += w * fmaxf(fmaf(Ag, fa1.y, fmaf(Ax, fb1.y, C)), 0.f);
    }
    *reinterpret_cast<float4*>(&d_z[n * S + p0 + tid * 4]) =
        make_float4(za[0], za[1], za[2], za[3]);

    float s = za[0] + za[1] + za[2] + za[3];
    float q = za[0]*za[0] + za[1]*za[1] + za[2]*za[2] + za[3]*za[3];
#pragma unroll
    for (int off = 16; off > 0; off >>= 1) {
        s += __shfl_down_sync(0xFFFFFFFFu, s, off);
        q += __shfl_down_sync(0xFFFFFFFFu, q, off);
    }
    __shared__ float rs[8], rq[8];
    int wid = tid >> 5, ln = tid & 31;
    if (ln == 0) { rs[wid] = s; rq[wid] = q; }
    __syncthreads();
    if (tid == 0) {
        float st = 0.f, qt = 0.f;
#pragma unroll
        for (int w2 = 0; w2 < 8; w2++) { st += rs[w2]; qt += rq[w2]; }
        atomicAdd(&d_zstat[n], st);
        atomicAdd(&d_zstat[NB + n], qt);
    }
}

// ---- fused alpha+mul: out = x * sigmoid(A*z+B) ------------------------------
__global__ void k_mul(const float* __restrict__ x, float* __restrict__ out,
                      const float* __restrict__ gam_p, const float* __restrict__ bet_p) {
    const int idx = blockIdx.x * blockDim.x + threadIdx.x;   // float4 index
    const int n   = idx >> 22;
    const int p4  = idx & (S / 4 - 1);
    const float inv = 1.f / (float)S;
    float m   = d_zstat[n] * inv;
    float var = fmaxf(d_zstat[NB + n] * inv - m * m, 0.f);
    float A   = gam_p[0] * rsqrtf(var + EPS);
    float B   = bet_p[0] - m * A;
    float4 z  = *reinterpret_cast<const float4*>(&d_z[n * S + p4 * 4]);
    float4 xv = reinterpret_cast<const float4*>(x)[idx];
    float4 o;
    o.x = xv.x / (1.f + __expf(-fmaf(A, z.x, B)));
    o.y = xv.y / (1.f + __expf(-fmaf(A, z.y, B)));
    o.z = xv.z / (1.f + __expf(-fmaf(A, z.z, B)));
    o.w = xv.w / (1.f + __expf(-fmaf(A, z.w, B)));
    reinterpret_cast<float4*>(out)[idx] = o;
}

// ============================================================================
extern "C" void kernel_launch(void* const* d_in, const int* in_sizes, int n_in,
                              void* d_out, int out_size) {
    const float* g     = (const float*)d_in[0];
    const float* x     = (const float*)d_in[1];
    const float* Wg    = (const float*)d_in[2];
    const float* Wx    = (const float*)d_in[3];
    const float* Wpsi  = (const float*)d_in[4];
    const float* gam_g = (const float*)d_in[5];
    const float* bet_g = (const float*)d_in[6];
    const float* gam_x = (const float*)d_in[7];
    const float* bet_x = (const float*)d_in[8];
    const float* gam_p = (const float*)d_in[9];
    const float* bet_p = (const float*)d_in[10];
    float* out = (float*)d_out;

    cudaFuncSetAttribute(k_gemm<G,  true >,
                         cudaFuncAttributeMaxDynamicSharedMemorySize, SM_TOT);
    cudaFuncSetAttribute(k_gemm<XC, false>,
                         cudaFuncAttributeMaxDynamicSharedMemorySize, SM_TOT);

    dim3 ggrid(S / 128, NB);                       // 1024 x 2

    // order keeps k_gemm<G> at launch slot 4 (ncu capture)
    k_wconv<<<128, 256>>>(Wg, Wx);
    k_gemm<XC, false><<<ggrid, 256, SM_TOT>>>(x);
    k_zero2<<<1, 32>>>();
    k_gemm<G,  true ><<<ggrid, 256, SM_TOT>>>(g);

    k_coefs<<<1, 256>>>(gam_g, bet_g, gam_x, bet_x);

    dim3 cgrid(S / 1024, NB);                      // 128 x 2
    k_combine<<<cgrid, 256>>>(Wpsi);

    int total4 = NB * XC * S / 4;                  // 16,777,216 float4
    k_mul<<<total4 / 256, 256>>>(x, out, gam_p, bet_p);
}

// round 13
// speedup vs baseline: 1.5187x; 1.1177x over previous
#include <cuda_runtime.h>
#include <cuda_fp16.h>

// ============================================================================
// AttentionGate3D — round 13: round-12 fusion with FIXED tile mapping.
// One GEMM kernel, grid (2048, NB): even bx -> x-GEMM (K=128) tile bx/2,
// odd bx -> g-GEMM (K=256) tile bx/2. 1024 tiles each per batch (correct).
// GEMM body = round-9 best, verbatim. coefs folded into combine. 4 launches.
// ============================================================================

#define EPS 1e-5f

constexpr int NB = 2;
constexpr int G  = 256;
constexpr int XC = 128;
constexpr int I  = 128;
constexpr int S  = 32 * 64 * 64;   // 131072

// ---- scratch ----
__device__ __half d_yg[NB * I * S];
__device__ __half d_yx[NB * I * S];
__device__ __align__(16) __half d_whg[I * G];
__device__ __align__(16) __half d_whx[I * XC];
__device__ float  d_z[NB * S];
__device__ float  d_sum_g[NB * I];
__device__ float  d_sq_g [NB * I];
__device__ float  d_sum_x[NB * I];
__device__ float  d_sq_x [NB * I];
__device__ float  d_zstat[2 * NB];

// ---- W fp32->fp16 pre-convert + ALL stat zeroing ----
__global__ void k_wconv(const float* __restrict__ Wg, const float* __restrict__ Wx) {
    int t = blockIdx.x * 256 + threadIdx.x;
    if (t < I * G)  d_whg[t] = __float2half_rn(Wg[t]);
    if (t < I * XC) d_whx[t] = __float2half_rn(Wx[t]);
    if (t < NB * I) {
        d_sum_g[t] = 0.f; d_sq_g[t] = 0.f;
        d_sum_x[t] = 0.f; d_sq_x[t] = 0.f;
    }
    if (t < 2 * NB) d_zstat[t] = 0.f;
}

// ---- MMA helpers ----
__device__ __forceinline__ void ldsm_x4(unsigned (&r)[4], unsigned addr) {
    asm volatile("ldmatrix.sync.aligned.m8n8.x4.shared.b16 {%0,%1,%2,%3}, [%4];"
        : "=r"(r[0]), "=r"(r[1]), "=r"(r[2]), "=r"(r[3]) : "r"(addr));
}
__device__ __forceinline__ void ldsm_x4_t(unsigned (&r)[4], unsigned addr) {
    asm volatile("ldmatrix.sync.aligned.m8n8.x4.trans.shared.b16 {%0,%1,%2,%3}, [%4];"
        : "=r"(r[0]), "=r"(r[1]), "=r"(r[2]), "=r"(r[3]) : "r"(addr));
}
__device__ __forceinline__ void mma16816(float (&d)[4], const unsigned (&a)[4],
                                         const unsigned (&b)[2]) {
    asm volatile("mma.sync.aligned.m16n8k16.row.col.f32.f16.f16.f32 "
        "{%0,%1,%2,%3}, {%4,%5,%6,%7}, {%8,%9}, {%0,%1,%2,%3};"
        : "+f"(d[0]), "+f"(d[1]), "+f"(d[2]), "+f"(d[3])
        : "r"(a[0]), "r"(a[1]), "r"(a[2]), "r"(a[3]), "r"(b[0]), "r"(b[1]));
}
union H2U { __half2 h; unsigned u; };
__device__ __forceinline__ unsigned pack2h(float a, float b) {
    H2U v; v.h = __floats2half2_rn(a, b); return v.u;
}
__device__ __forceinline__ void cp16(unsigned dst, const void* src) {
    asm volatile("cp.async.cg.shared.global [%0], [%1], 16;" :: "r"(dst), "l"(src));
}
__device__ __forceinline__ void cp_commit() {
    asm volatile("cp.async.commit_group;" ::: "memory");
}
template<int N>
__device__ __forceinline__ void cp_wait() {
    asm volatile("cp.async.wait_group %0;" :: "n"(N) : "memory");
}

// ---- GEMM body (round-9, verbatim): y[n,i,p] = sum_c W[i,c]*src[n,c,p] ----
// CTA tile M=128(i) x N=128(p); 8 warps = 2(M) x 4(N), warp 64M x 32N.
// K in 32-chunks. smem: sS (B fp32) 3 x 16KB | sAh (W fp16) 4 x 8KB |
// sBh 2 x 8KB = 96KB.
template<int K, bool ISG>
__device__ __forceinline__ void gemm_body(const float* __restrict__ src,
                                          char* smem, int n, int p0) {
    constexpr int NIT2 = K / 32;
    const unsigned sS32  = (unsigned)__cvta_generic_to_shared(smem);
    const unsigned sAh32 = (unsigned)__cvta_generic_to_shared(smem + 49152);
    const unsigned sBh32 = (unsigned)__cvta_generic_to_shared(smem + 81920);
    float*  sS  = reinterpret_cast<float*>(smem);
    __half* sBh = reinterpret_cast<__half*>(smem + 81920);

    const __half* wh  = ISG ? d_whg   : d_whx;
    __half* yout = ISG ? d_yg    : d_yx;
    float*  ssum = ISG ? d_sum_g : d_sum_x;
    float*  ssq  = ISG ? d_sq_g  : d_sq_x;

    const int tid  = threadIdx.x;
    const int warp = tid >> 5, lane = tid & 31;
    const int wm = warp >> 2, wn = warp & 3;
    const float* srcn = src + (size_t)n * K * S + p0;

    // B staging role: channel cst (0..15 -> rows cst, cst+16), pts pb (0..15)
    const int cst = tid >> 4;
    const int pb  = tid & 15;
    const float* gp = srcn + (size_t)cst * S + pb * 4;
    const unsigned myoffB = (unsigned)(cst * 512 + pb * 16);
    // A staging role: row arow (0..127), quarter-pair ah (0/1)
    const int arow = tid >> 1, ah = tid & 1;
    const __half* wsrc = wh + (size_t)arow * K + ah * 8;
    const unsigned myoffA = (unsigned)(arow * 16);

    auto issue = [&](int it) {
        unsigned dstB = sS32 + (unsigned)((it % 3) * 16384) + myoffB;
        const float* s0 = gp + (size_t)it * 32 * S;
        cp16(dstB, s0);
        cp16(dstB + 256, s0 + 64);
        cp16(dstB + 8192, s0 + (size_t)16 * S);
        cp16(dstB + 8192 + 256, s0 + (size_t)16 * S + 64);
        unsigned dstA = sAh32 + (unsigned)((it & 3) * 8192) + myoffA;
        const __half* w0 = wsrc + it * 32;
        cp16(dstA + ah * 2048, w0);
        cp16(dstA + (2 + ah) * 2048, w0 + 16);
    };

    issue(0); cp_commit();
    issue(1); cp_commit();
    issue(2); cp_commit();

    float acc[4][4][4] = {};

    const int swz  = ((pb >> 1) ^ (cst & 7));
    const int sts0 = (cst * 128 + (swz << 3)       + ((pb & 1) << 2)) * 2;
    const int sts1 = (cst * 128 + ((8 + swz) << 3) + ((pb & 1) << 2)) * 2;

    for (int it = 0; it < NIT2; it++) {
        cp_wait<2>();                    // group `it` landed (thread-private)
        const float4* rp = reinterpret_cast<const float4*>(
            sS + (it % 3) * 4096 + cst * 128 + pb * 4);
        float4 w0 = rp[0];
        float4 w1 = rp[16];
        float4 w2 = rp[512];
        float4 w3 = rp[528];
        {
            char* sb = reinterpret_cast<char*>(sBh) + (it & 1) * 8192;
            uint2 u;
            u.x = pack2h(w0.x, w0.y); u.y = pack2h(w0.z, w0.w);
            *reinterpret_cast<uint2*>(sb + sts0) = u;
            u.x = pack2h(w1.x, w1.y); u.y = pack2h(w1.z, w1.w);
            *reinterpret_cast<uint2*>(sb + sts1) = u;
            u.x = pack2h(w2.x, w2.y); u.y = pack2h(w2.z, w2.w);
            *reinterpret_cast<uint2*>(sb + 4096 + sts0) = u;
            u.x = pack2h(w3.x, w3.y); u.y = pack2h(w3.z, w3.w);
            *reinterpret_cast<uint2*>(sb + 4096 + sts1) = u;
        }
        __syncthreads();
        if (it + 3 < NIT2) issue(it + 3);
        cp_commit();

        const unsigned sbb = sBh32 + (unsigned)((it & 1) * 8192);
        const unsigned saa = sAh32 + (unsigned)((it & 3) * 8192);
#pragma unroll
        for (int kh2 = 0; kh2 < 2; kh2++) {
            unsigned afr[4][4];
#pragma unroll
            for (int tm = 0; tm < 4; tm++) {
                int row = wm * 64 + tm * 16 + (lane & 15);
                ldsm_x4(afr[tm], saa + (unsigned)(kh2 * 4096 +
                         (lane >> 4) * 2048 + row * 16));
            }
            unsigned bfr[4][2];
#pragma unroll
            for (int h = 0; h < 2; h++) {
                int nbX  = 2 * h + ((lane >> 4) & 1);
                int c    = ((lane >> 3) & 1) * 8 + (lane & 7);
                int phys = (wn * 4 + nbX) ^ (lane & 7);
                unsigned r4[4];
                ldsm_x4_t(r4, sbb + (unsigned)(kh2 * 4096 +
                          (c * 128 + phys * 8) * 2));
                bfr[2 * h][0]     = r4[0]; bfr[2 * h][1]     = r4[1];
                bfr[2 * h + 1][0] = r4[2]; bfr[2 * h + 1][1] = r4[3];
            }
#pragma unroll
            for (int tm = 0; tm < 4; tm++)
#pragma unroll
                for (int tn = 0; tn < 4; tn++)
                    mma16816(acc[tm][tn], afr[tm], bfr[tn]);
        }
    }

    // epilogue: fp16 store + per-i stats from fp32 accumulators
    __half* yn = yout + (size_t)n * I * S + p0;
#pragma unroll
    for (int tm = 0; tm < 4; tm++) {
        int r1 = wm * 64 + tm * 16 + (lane >> 2);
        float s1 = 0.f, q1 = 0.f, s2 = 0.f, q2 = 0.f;
#pragma unroll
        for (int tn = 0; tn < 4; tn++) {
            float* c = acc[tm][tn];
            int col = wn * 32 + tn * 8 + (lane & 3) * 2;
            *reinterpret_cast<__half2*>(yn + (size_t)r1 * S + col) =
                __floats2half2_rn(c[0], c[1]);
            *reinterpret_cast<__half2*>(yn + (size_t)(r1 + 8) * S + col) =
                __floats2half2_rn(c[2], c[3]);
            s1 += c[0] + c[1]; q1 += c[0] * c[0] + c[1] * c[1];
            s2 += c[2] + c[3]; q2 += c[2] * c[2] + c[3] * c[3];
        }
#pragma unroll
        for (int off = 2; off > 0; off >>= 1) {
            s1 += __shfl_down_sync(0xFFFFFFFFu, s1, off, 4);
            q1 += __shfl_down_sync(0xFFFFFFFFu, q1, off, 4);
            s2 += __shfl_down_sync(0xFFFFFFFFu, s2, off, 4);
            q2 += __shfl_down_sync(0xFFFFFFFFu, q2, off, 4);
        }
        if ((lane & 3) == 0) {
            atomicAdd(&ssum[n * I + r1], s1);
            atomicAdd(&ssq [n * I + r1], q1);
            atomicAdd(&ssum[n * I + r1 + 8], s2);
            atomicAdd(&ssq [n * I + r1 + 8], q2);
        }
    }
}

// ---- fused GEMM: even bx -> x-GEMM, odd bx -> g-GEMM (1024 tiles each) ----
__global__ void __launch_bounds__(256, 2) k_gemm_fused(const float* __restrict__ g,
                                                       const float* __restrict__ x) {
    extern __shared__ __align__(16) char smem[];
    const int bx = blockIdx.x;
    const int n  = blockIdx.y;
    const int p0 = (bx >> 1) * 128;                // tile 0..1023
    if ((bx & 1) == 0) {
        gemm_body<XC, false>(x, smem, n, p0);
    } else {
        gemm_body<G, true>(g, smem, n, p0);
    }
}

// ---- combine (coefs computed per-block): z = Wpsi . relu(...), + z stats ---
__global__ void __launch_bounds__(256) k_combine(
        const float* __restrict__ Wpsi,
        const float* __restrict__ gam_g, const float* __restrict__ bet_g,
        const float* __restrict__ gam_x, const float* __restrict__ bet_x) {
    __shared__ float sc[5 * I];
    const int tid = threadIdx.x;
    const int n   = blockIdx.y;
    const int p0  = blockIdx.x * 1024;
    if (tid < I) {
        const float inv = 1.f / (float)S;
        float m   = d_sum_g[n * I + tid] * inv;
        float var = fmaxf(d_sq_g[n * I + tid] * inv - m * m, 0.f);
        float A   = gam_g[tid] * rsqrtf(var + EPS);
        sc[tid]     = A;
        sc[I + tid] = bet_g[tid] - m * A;
        m   = d_sum_x[n * I + tid] * inv;
        var = fmaxf(d_sq_x[n * I + tid] * inv - m * m, 0.f);
        A   = gam_x[tid] * rsqrtf(var + EPS);
        sc[2 * I + tid] = A;
        sc[3 * I + tid] = bet_x[tid] - m * A;
        sc[4 * I + tid] = Wpsi[tid];
    }
    __syncthreads();
    const __half* ygb = d_yg + (size_t)n * I * S + p0 + tid * 4;
    const __half* yxb = d_yx + (size_t)n * I * S + p0 + tid * 4;
    float za[4] = {0.f, 0.f, 0.f, 0.f};

#pragma unroll 4
    for (int i = 0; i < I; i++) {
        uint2 ua = *reinterpret_cast<const uint2*>(ygb + (size_t)i * S);
        uint2 ub = *reinterpret_cast<const uint2*>(yxb + (size_t)i * S);
        float Ag = sc[i], Ax = sc[2 * I + i];
        float C  = sc[I + i] + sc[3 * I + i];
        float w  = sc[4 * I + i];
        H2U a0, a1, b0, b1;
        a0.u = ua.x; a1.u = ua.y; b0.u = ub.x; b1.u = ub.y;
        float2 fa0 = __half22float2(a0.h), fa1 = __half22float2(a1.h);
        float2 fb0 = __half22float2(b0.h), fb1 = __half22float2(b1.h);
        za[0] += w * fmaxf(fmaf(Ag, fa0.x, fmaf(Ax, fb0.x, C)), 0.f);
        za[1] += w * fmaxf(fmaf(Ag, fa0.y, fmaf(Ax, fb0.y, C)), 0.f);
        za[2] += w * fmaxf(fmaf(Ag, fa1.x, fmaf(Ax, fb1.x, C)), 0.f);
        za[3] += w * fmaxf(fmaf(Ag, fa1.y, fmaf(Ax, fb1.y, C)), 0.f);
    }
    *reinterpret_cast<float4*>(&d_z[n * S + p0 + tid * 4]) =
        make_float4(za[0], za[1], za[2], za[3]);

    float s = za[0] + za[1] + za[2] + za[3];
    float q = za[0]*za[0] + za[1]*za[1] + za[2]*za[2] + za[3]*za[3];
#pragma unroll
    for (int off = 16; off > 0; off >>= 1) {
        s += __shfl_down_sync(0xFFFFFFFFu, s, off);
        q += __shfl_down_sync(0xFFFFFFFFu, q, off);
    }
    __shared__ float rs[8], rq[8];
    int wid = tid >> 5, ln = tid & 31;
    if (ln == 0) { rs[wid] = s; rq[wid] = q; }
    __syncthreads();
    if (tid == 0) {
        float st = 0.f, qt = 0.f;
#pragma unroll
        for (int w2 = 0; w2 < 8; w2++) { st += rs[w2]; qt += rq[w2]; }
        atomicAdd(&d_zstat[n], st);
        atomicAdd(&d_zstat[NB + n], qt);
    }
}

// ---- fused alpha+mul: out = x * sigmoid(A*z+B) ------------------------------
__global__ void k_mul(const float* __restrict__ x, float* __restrict__ out,
                      const float* __restrict__ gam_p, const float* __restrict__ bet_p) {
    const int idx = blockIdx.x * blockDim.x + threadIdx.x;   // float4 index
    const int n   = idx >> 22;
    const int p4  = idx & (S / 4 - 1);
    const float inv = 1.f / (float)S;
    float m   = d_zstat[n] * inv;
    float var = fmaxf(d_zstat[NB + n] * inv - m * m, 0.f);
    float A   = gam_p[0] * rsqrtf(var + EPS);
    float B   = bet_p[0] - m * A;
    float4 z  = *reinterpret_cast<const float4*>(&d_z[n * S + p4 * 4]);
    float4 xv = reinterpret_cast<const float4*>(x)[idx];
    float4 o;
    o.x = xv.x / (1.f + __expf(-fmaf(A, z.x, B)));
    o.y = xv.y / (1.f + __expf(-fmaf(A, z.y, B)));
    o.z = xv.z / (1.f + __expf(-fmaf(A, z.z, B)));
    o.w = xv.w / (1.f + __expf(-fmaf(A, z.w, B)));
    reinterpret_cast<float4*>(out)[idx] = o;
}

// ============================================================================
extern "C" void kernel_launch(void* const* d_in, const int* in_sizes, int n_in,
                              void* d_out, int out_size) {
    const float* g     = (const float*)d_in[0];
    const float* x     = (const float*)d_in[1];
    const float* Wg    = (const float*)d_in[2];
    const float* Wx    = (const float*)d_in[3];
    const float* Wpsi  = (const float*)d_in[4];
    const float* gam_g = (const float*)d_in[5];
    const float* bet_g = (const float*)d_in[6];
    const float* gam_x = (const float*)d_in[7];
    const float* bet_x = (const float*)d_in[8];
    const float* gam_p = (const float*)d_in[9];
    const float* bet_p = (const float*)d_in[10];
    float* out = (float*)d_out;

    const int SMEM = 49152 + 32768 + 16384;        // 98304
    cudaFuncSetAttribute(k_gemm_fused,
                         cudaFuncAttributeMaxDynamicSharedMemorySize, SMEM);

    k_wconv<<<128, 256>>>(Wg, Wx);

    dim3 ggrid(2048, NB);              // per n: 1024 x-tiles + 1024 g-tiles
    k_gemm_fused<<<ggrid, 256, SMEM>>>(g, x);

    dim3 cgrid(S / 1024, NB);                      // 128 x 2
    k_combine<<<cgrid, 256>>>(Wpsi, gam_g, bet_g, gam_x, bet_x);

    int total4 = NB * XC * S / 4;                  // 16,777,216 float4
    k_mul<<<total4 / 256, 256>>>(x, out, gam_p, bet_p);
}